// round 13
// baseline (speedup 1.0000x reference)
#include <cuda_runtime.h>
#include <math.h>

// ---------------------------------------------------------------------------
// DCWTv2InferenceCache: segment-tree cover-set attention decode step.
// ONE kernel (per-kernel node cost ~6us measured; fork/join overlap disproven):
//   grid 1216, launch_bounds(256,4):
//     blocks 0..15           : local-window attention, then join stream
//     blocks 16..16+16*nSmall: small-node attention, then join stream
//     all blocks             : work-stealing HBM stream (chunk means -> g_f)
//     blocks 0..16*nBig-1    : after stream drains (g_done spin), big-node
//                              attention from L2-hot g_f.
// Graph = memset(d_out) + memset(g_f/g_sync) + 1 kernel.
// ---------------------------------------------------------------------------

#define TOKDIM   1024            // 16 heads * 64 dims
#define HEADS    16
#define HDIM     64
#define MAXBIG   16
#define MAXNODES 40
#define GRID_M   1216
#define BATCH    16              // units per dynamic grab

__device__ float g_f[(size_t)MAXBIG * 64 * TOKDIM];
__device__ unsigned int g_sync[2];   // [0]=work counter, [1]=done counter

struct PartParams {
    int  nBig;
    int  a[MAXBIG];              // token offset of node
    int  C[MAXBIG];              // chunks (of 64 tokens) in node
    float inv[MAXBIG];           // 1/C
    long unitBase[MAXBIG + 1];   // prefix of C[n]*64 units
};

struct NodeParams {
    int   nSmall;
    int   sdepth[MAXNODES];
    int   sK[MAXNODES];
    int   soff[MAXNODES];        // token offset in V
    int   nBig;
    int   bdepth[MAXBIG];
    float inv_n;
};

__global__ void __launch_bounds__(256, 4) mega_kernel(
    const float* __restrict__ V,
    const float* __restrict__ q,
    const float* __restrict__ W,
    const float* __restrict__ temp,
    PartParams bp, NodeParams np, int pos, long U,
    float* __restrict__ out)
{
    const int bid = blockIdx.x;
    const int tid = threadIdx.x;

    __shared__ float fW[64 * 65];       // W / f-tile buffer (reused per phase)
    __shared__ float s_sh[512];
    __shared__ float red[256];
    __shared__ float q_sh[HDIM];
    __shared__ float qd[HDIM];
    __shared__ float s_scale, s_mx, s_sum;
    __shared__ unsigned int sh_u;

    const int nPre = HEADS + np.nSmall * HEADS;

    // ================= Phase A: attention pre-work (blocks 0..nPre-1) =======
    if (bid < HEADS) {
        // ---- local-window attention, head h = bid ----
        const int h    = bid;
        const int nloc = pos < 512 ? pos : 512;
        const int base = pos - nloc;

        if (tid < HDIM) q_sh[tid] = q[h * HDIM + tid];
        s_sh[tid]       = -1e30f;
        s_sh[tid + 256] = -1e30f;
        __syncthreads();

        // per-thread scores, 2 tokens/thread, 16 independent float4 each
        for (int t = tid; t < nloc; t += 256) {
            const float4* vp = (const float4*)(V + (long)(base + t) * TOKDIM + h * HDIM);
            const float4* qp = (const float4*)q_sh;
            float acc = 0.f;
            #pragma unroll
            for (int i = 0; i < 16; i++) {
                float4 x  = vp[i];
                float4 qq = qp[i];
                acc += x.x * qq.x + x.y * qq.y + x.z * qq.z + x.w * qq.w;
            }
            s_sh[t] = acc * 0.125f;            // 1/sqrt(64)
        }
        __syncthreads();

        red[tid] = fmaxf(s_sh[tid], s_sh[tid + 256]);
        __syncthreads();
        #pragma unroll
        for (int st = 128; st >= 32; st >>= 1) {
            if (tid < st) red[tid] = fmaxf(red[tid], red[tid + st]);
            __syncthreads();
        }
        if (tid < 32) {
            float m = red[tid];
            #pragma unroll
            for (int o = 16; o > 0; o >>= 1)
                m = fmaxf(m, __shfl_xor_sync(0xffffffff, m, o));
            if (tid == 0) s_mx = m;
        }
        __syncthreads();

        float lsum = 0.f;
        #pragma unroll
        for (int t = tid; t < 512; t += 256) {
            float e = (t < nloc) ? expf(s_sh[t] - s_mx) : 0.f;
            s_sh[t] = e;
            lsum += e;
        }
        red[tid] = lsum;
        __syncthreads();
        #pragma unroll
        for (int st = 128; st >= 32; st >>= 1) {
            if (tid < st) red[tid] += red[tid + st];
            __syncthreads();
        }
        if (tid < 32) {
            float sm = red[tid];
            #pragma unroll
            for (int o = 16; o > 0; o >>= 1)
                sm += __shfl_xor_sync(0xffffffff, sm, o);
            if (tid == 0) s_sum = sm;
        }
        __syncthreads();

        {
            int g = tid >> 6, d = tid & 63;
            float acc = 0.f;
            #pragma unroll 8
            for (int k = g; k < nloc; k += 4)
                acc += s_sh[k] * V[(long)(base + k) * TOKDIM + h * HDIM + d];
            red[tid] = acc;
        }
        __syncthreads();
        if (tid < HDIM) {
            float o = (red[tid] + red[64 + tid]) + (red[128 + tid] + red[192 + tid]);
            atomicAdd(out + h * HDIM + tid, (s_sum > 0.f) ? (o / s_sum) : 0.f);
        }
        __syncthreads();
    } else if (bid < nPre) {
        // ---- small cover-set node attention ----
        const int si    = (bid - HEADS) >> 4;
        const int h     = (bid - HEADS) & 15;
        const int depth = np.sdepth[si];
        const int K     = np.sK[si];

        if (tid < HDIM) q_sh[tid] = q[h * HDIM + tid];

        const float* Wd = W + (long)depth * HDIM * HDIM;
        #pragma unroll
        for (int i = tid; i < HDIM * HDIM; i += 256) {
            int d = i >> 6, e = i & 63;
            fW[e * 65 + d] = Wd[i];            // coalesced, transposed
        }
        if (tid == 0) {
            float t  = temp[depth];
            float sp = log1pf(expf(t));        // softplus
            s_scale  = 1.0f / ((sp + 1e-6f) * 8.0f);
        }
        __syncthreads();

        if (tid < HDIM) {
            float acc = q_sh[tid];
            #pragma unroll
            for (int e = 0; e < HDIM; e++) acc += q_sh[e] * fW[e * 65 + tid];
            qd[tid] = acc;
        }
        __syncthreads();   // fW free

        const float* fsrc = V + (long)np.soff[si] * TOKDIM;
        for (int i = tid; i < K * HDIM; i += 256) {
            int k = i >> 6, d = i & 63;
            fW[k * 65 + d] = fsrc[(long)k * TOKDIM + h * HDIM + d];
        }
        __syncthreads();

        float sc = -1e30f;
        if (tid < K) {
            float acc = 0.f;
            #pragma unroll
            for (int d = 0; d < HDIM; d++) acc += qd[d] * fW[tid * 65 + d];
            sc = acc * s_scale;
        }
        if (tid < 64) red[tid] = sc;
        __syncthreads();
        if (tid < 32) {
            float m = fmaxf(red[tid], red[tid + 32]);
            #pragma unroll
            for (int o = 16; o > 0; o >>= 1)
                m = fmaxf(m, __shfl_xor_sync(0xffffffff, m, o));
            if (tid == 0) s_mx = m;
        }
        __syncthreads();

        float e = (tid < K) ? expf(sc - s_mx) : 0.f;
        if (tid < 64) { s_sh[tid] = e; red[tid] = e; }
        __syncthreads();
        if (tid < 32) {
            float sm = red[tid] + red[tid + 32];
            #pragma unroll
            for (int o = 16; o > 0; o >>= 1)
                sm += __shfl_xor_sync(0xffffffff, sm, o);
            if (tid == 0) s_sum = sm;
        }
        __syncthreads();

        {
            int g = tid >> 6, d = tid & 63;
            float acc = 0.f;
            for (int k = g; k < K; k += 4) acc += s_sh[k] * fW[k * 65 + d];
            red[tid] = acc;
        }
        __syncthreads();
        if (tid < HDIM) {
            float o = (red[tid] + red[64 + tid]) + (red[128 + tid] + red[192 + tid]);
            atomicAdd(out + h * HDIM + tid, (o / s_sum) * np.inv_n);
        }
        __syncthreads();
    }

    // ================= Phase B: work-stealing HBM stream =====================
    if (U > 0) {
        for (;;) {
            if (tid == 0) sh_u = atomicAdd(&g_sync[0], BATCH);
            __syncthreads();
            long u = (long)sh_u;
            if (u >= U) break;
            long u1 = u + BATCH; if (u1 > U) u1 = U;
            __syncthreads();        // protect sh_u before next grab

            while (u < u1) {
                int n = 0;
                while (u >= bp.unitBase[n + 1]) n++;
                long rem = u - bp.unitBase[n];
                int  k   = (int)(rem / bp.C[n]);
                int  c   = (int)(rem % bp.C[n]);
                long run = bp.C[n] - c;
                if (run > u1 - u) run = u1 - u;

                const float4* p = (const float4*)(V + ((long)bp.a[n] + (long)c * 64 + k) * TOKDIM) + tid;
                const long STR = 64L * TOKDIM / 4;

                float4 a0 = {0,0,0,0}, a1 = {0,0,0,0}, a2 = {0,0,0,0}, a3 = {0,0,0,0};
                long r = 0;
                for (; r + 8 <= run; r += 8) {
                    float4 x0 = p[0];
                    float4 x1 = p[STR];
                    float4 x2 = p[2 * STR];
                    float4 x3 = p[3 * STR];
                    float4 x4 = p[4 * STR];
                    float4 x5 = p[5 * STR];
                    float4 x6 = p[6 * STR];
                    float4 x7 = p[7 * STR];
                    a0.x += x0.x; a0.y += x0.y; a0.z += x0.z; a0.w += x0.w;
                    a1.x += x1.x; a1.y += x1.y; a1.z += x1.z; a1.w += x1.w;
                    a2.x += x2.x; a2.y += x2.y; a2.z += x2.z; a2.w += x2.w;
                    a3.x += x3.x; a3.y += x3.y; a3.z += x3.z; a3.w += x3.w;
                    a0.x += x4.x; a0.y += x4.y; a0.z += x4.z; a0.w += x4.w;
                    a1.x += x5.x; a1.y += x5.y; a1.z += x5.z; a1.w += x5.w;
                    a2.x += x6.x; a2.y += x6.y; a2.z += x6.z; a2.w += x6.w;
                    a3.x += x7.x; a3.y += x7.y; a3.z += x7.z; a3.w += x7.w;
                    p += 8 * STR;
                }
                for (; r < run; r++) {
                    float4 x0 = p[0];
                    a0.x += x0.x; a0.y += x0.y; a0.z += x0.z; a0.w += x0.w;
                    p += STR;
                }
                float s = bp.inv[n];
                float* o = g_f + ((long)n * 64 + k) * TOKDIM + tid * 4;
                atomicAdd(o + 0, ((a0.x + a1.x) + (a2.x + a3.x)) * s);
                atomicAdd(o + 1, ((a0.y + a1.y) + (a2.y + a3.y)) * s);
                atomicAdd(o + 2, ((a0.z + a1.z) + (a2.z + a3.z)) * s);
                atomicAdd(o + 3, ((a0.w + a1.w) + (a2.w + a3.w)) * s);
                u += run;
            }
        }

        // ================= Phase C: completion + big-node tail ===============
        __threadfence();
        __syncthreads();
        if (tid == 0) atomicAdd(&g_sync[1], 1u);

        if (bid < np.nBig * HEADS) {
            const int bi = bid >> 4;
            const int h  = bid & 15;
            const int depth = np.bdepth[bi];

            // overlap the spin-independent loads: q and W first
            if (tid < HDIM) q_sh[tid] = q[h * HDIM + tid];
            const float* Wd = W + (long)depth * HDIM * HDIM;
            #pragma unroll
            for (int i = tid; i < HDIM * HDIM; i += 256) {
                int d = i >> 6, e = i & 63;
                fW[e * 65 + d] = Wd[i];
            }
            if (tid == 0) {
                float t  = temp[depth];
                float sp = log1pf(expf(t));
                s_scale  = 1.0f / ((sp + 1e-6f) * 8.0f);
            }
            __syncthreads();
            if (tid < HDIM) {
                float acc = q_sh[tid];
                #pragma unroll
                for (int e = 0; e < HDIM; e++) acc += q_sh[e] * fW[e * 65 + tid];
                qd[tid] = acc;
            }

            // wait for the whole stream to drain
            if (tid == 0) {
                volatile unsigned int* dp = &g_sync[1];
                while (*dp < (unsigned int)GRID_M) __nanosleep(256);
            }
            __syncthreads();
            __threadfence();

            // f tile from L2-hot g_f, float4 bursts into padded smem
            const float* fsrc = g_f + (long)bi * 64 * TOKDIM + h * HDIM;
            #pragma unroll
            for (int i = tid; i < 64 * 16; i += 256) {
                int k = i >> 4, j = i & 15;
                float4 v = *(const float4*)(fsrc + (long)k * TOKDIM + j * 4);
                int d = j * 4;
                fW[k * 65 + d + 0] = v.x;
                fW[k * 65 + d + 1] = v.y;
                fW[k * 65 + d + 2] = v.z;
                fW[k * 65 + d + 3] = v.w;
            }
            __syncthreads();

            float sc = -1e30f;
            if (tid < 64) {
                float acc = 0.f;
                #pragma unroll
                for (int d = 0; d < HDIM; d++) acc += qd[d] * fW[tid * 65 + d];
                sc = acc * s_scale;
            }
            if (tid < 64) red[tid] = sc;
            __syncthreads();
            if (tid < 32) {
                float m = fmaxf(red[tid], red[tid + 32]);
                #pragma unroll
                for (int o = 16; o > 0; o >>= 1)
                    m = fmaxf(m, __shfl_xor_sync(0xffffffff, m, o));
                if (tid == 0) s_mx = m;
            }
            __syncthreads();

            float e = (tid < 64) ? expf(sc - s_mx) : 0.f;
            if (tid < 64) { s_sh[tid] = e; red[tid] = e; }
            __syncthreads();
            if (tid < 32) {
                float sm = red[tid] + red[tid + 32];
                #pragma unroll
                for (int o = 16; o > 0; o >>= 1)
                    sm += __shfl_xor_sync(0xffffffff, sm, o);
                if (tid == 0) s_sum = sm;
            }
            __syncthreads();

            {
                int g = tid >> 6, d = tid & 63;
                float acc = 0.f;
                for (int k = g; k < 64; k += 4) acc += s_sh[k] * fW[k * 65 + d];
                red[tid] = acc;
            }
            __syncthreads();
            if (tid < HDIM) {
                float o = (red[tid] + red[64 + tid]) + (red[128 + tid] + red[192 + tid]);
                atomicAdd(out + h * HDIM + tid, (o / s_sum) * np.inv_n);
            }
        }
    }
}

// ---------------------------------------------------------------------------
extern "C" void kernel_launch(void* const* d_in, const int* in_sizes, int n_in,
                              void* d_out, int out_size)
{
    const float* V    = (const float*)d_in[0];
    const float* q    = (const float*)d_in[1];
    const float* W    = (const float*)d_in[2];
    const float* temp = (const float*)d_in[3];

    const int pos = in_sizes[0] / TOKDIM;

    const int  LOG_N      = 17;
    const long LEAF_START = 1L << LOG_N;
    const long MAX_LEN    = 65536;

    PartParams bp; bp.nBig = 0;
    NodeParams np; np.nSmall = 0; np.nBig = 0;
    int nTotal = 0;

    auto addNode = [&](long idx) {
        int fl = 0; long t = idx;
        while (t > 1) { t >>= 1; fl++; }
        int depth = LOG_N - fl;
        long L = 1L << depth;
        long a = (idx << depth) - LEAF_START;
        nTotal++;
        if (L > 64) {
            int bi = bp.nBig++;
            bp.a[bi]   = (int)a;
            bp.C[bi]   = (int)(L / 64);
            bp.inv[bi] = 1.0f / (float)(L / 64);
            np.bdepth[np.nBig++] = depth;
        } else {
            int si = np.nSmall++;
            np.sdepth[si] = depth;
            np.sK[si]     = (int)L;
            np.soff[si]   = (int)a;
        }
    };

    long l = LEAF_START;
    long r = LEAF_START + (pos < MAX_LEN ? (long)pos : MAX_LEN);
    while (l < r) {
        if (l & 1) { addNode(l); l++; }
        if (r & 1) { r--; addNode(r); }
        l >>= 1; r >>= 1;
    }
    np.inv_n = nTotal > 0 ? 1.0f / (float)nTotal : 0.f;

    bp.unitBase[0] = 0;
    for (int i = 0; i < bp.nBig; i++)
        bp.unitBase[i + 1] = bp.unitBase[i] + (long)bp.C[i] * 64;
    long U = bp.nBig ? bp.unitBase[bp.nBig] : 0;

    cudaMemsetAsync(d_out, 0, (size_t)out_size * sizeof(float));
    if (bp.nBig > 0) {
        void* gf_ptr = nullptr; void* sync_ptr = nullptr;
        cudaGetSymbolAddress(&gf_ptr, g_f);
        cudaGetSymbolAddress(&sync_ptr, g_sync);
        cudaMemsetAsync(gf_ptr, 0, (size_t)bp.nBig * 64 * TOKDIM * sizeof(float));
        cudaMemsetAsync(sync_ptr, 0, 2 * sizeof(unsigned int));
    }

    mega_kernel<<<GRID_M, 256>>>(V, q, W, temp, bp, np, pos, U, (float*)d_out);
}